// round 6
// baseline (speedup 1.0000x reference)
#include <cuda_runtime.h>
#include <cuda_fp16.h>
#include <cstdint>

// ============================================================================
// B=8, N=4096, D=256, QK=128, M=32
//   Q = H0 @ Wq ; K = X0 @ Wk          (f16 GEMM, e4m3 output)
//   sumexp[b,n] = sum_m exp(scale * Q[b,n,:]·K[b,m,:])     (fp8 MMA)
//   out[b,m,:] = (sum_n slotw[m,n]*sumexp[b,n]*H0[b,n,:])
//              / (sum_n slotw[m,n]*sumexp[b,n] + 1e-6 * sum_n sumexp[b,n])
// R6: f16x2 ex2 (half MUFU) + phase-split exp/MMA interleave (no extra regs),
//     3-stage cp.async ring with one barrier per chunk, out_accum regridded,
//     micro kernel folded into reduce_out.
// ============================================================================

#define Bdim 8
#define Ndim 4096
#define Ddim 256
#define QKdim 128
#define Mdim 32

__device__ unsigned char g_Q8[Bdim * Ndim * QKdim];   // 4 MB e4m3
__device__ unsigned char g_K8[Bdim * Ndim * QKdim];   // 4 MB e4m3
__device__ __half g_Wt[2][QKdim * Ddim];
__device__ float g_sumexp[Bdim * Ndim];
__device__ float g_tsum[Bdim * 32];                   // per n-tile sumexp totals
__device__ float g_slotw[Mdim * Ndim];
__device__ float g_csum[Bdim * 64 * Mdim];            // per-chunk coef sums
__device__ float g_part[Bdim * 64 * Mdim * Ddim];     // 16 MB partials

// ---------------------------------------------------------------------------
// helpers
// ---------------------------------------------------------------------------
__device__ __forceinline__ uint32_t smem_u32(const void* p) {
    uint32_t a;
    asm("{ .reg .u64 t; cvta.to.shared.u64 t, %1; cvt.u32.u64 %0, t; }" : "=r"(a) : "l"(p));
    return a;
}
__device__ __forceinline__ uint16_t cvt_e4m3x2(float hi, float lo) {
    uint16_t r;
    asm("cvt.rn.satfinite.e4m3x2.f32 %0, %1, %2;" : "=h"(r) : "f"(hi), "f"(lo));
    return r;
}
#define CP_ASYNC16(dst, src) \
    asm volatile("cp.async.cg.shared.global [%0], [%1], 16;" :: "r"(dst), "l"(src))
#define CP_COMMIT() asm volatile("cp.async.commit_group;" ::: "memory")
#define CP_WAIT1()  asm volatile("cp.async.wait_group 1;" ::: "memory")

__device__ __forceinline__ void ldsm_x4(uint32_t* r, uint32_t addr) {
    asm volatile("ldmatrix.sync.aligned.m8n8.x4.shared.b16 {%0,%1,%2,%3}, [%4];"
                 : "=r"(r[0]), "=r"(r[1]), "=r"(r[2]), "=r"(r[3]) : "r"(addr));
}
__device__ __forceinline__ void mma_f16(float* c, const uint32_t* a, const uint32_t* b) {
    asm volatile(
        "mma.sync.aligned.m16n8k16.row.col.f32.f16.f16.f32 "
        "{%0,%1,%2,%3}, {%4,%5,%6,%7}, {%8,%9}, {%0,%1,%2,%3};"
        : "+f"(c[0]), "+f"(c[1]), "+f"(c[2]), "+f"(c[3])
        : "r"(a[0]), "r"(a[1]), "r"(a[2]), "r"(a[3]), "r"(b[0]), "r"(b[1]));
}
__device__ __forceinline__ void mma_fp8(float* c, const uint32_t* a, const uint32_t* b) {
    asm volatile(
        "mma.sync.aligned.m16n8k32.row.col.f32.e4m3.e4m3.f32 "
        "{%0,%1,%2,%3}, {%4,%5,%6,%7}, {%8,%9}, {%0,%1,%2,%3};"
        : "+f"(c[0]), "+f"(c[1]), "+f"(c[2]), "+f"(c[3])
        : "r"(a[0]), "r"(a[1]), "r"(a[2]), "r"(a[3]), "r"(b[0]), "r"(b[1]));
}

// f16x2 exp drain of one 4-value tile into h2 accumulators (slots mi*2, mi*2+1)
__device__ __forceinline__ void drain_tile(const float* ct, uint32_t* hacc, int mi,
                                           uint32_t cexh2) {
    uint32_t p0, p1;
    asm("cvt.rn.f16x2.f32 %0, %1, %2;" : "=r"(p0) : "f"(ct[1]), "f"(ct[0]));
    asm("cvt.rn.f16x2.f32 %0, %1, %2;" : "=r"(p1) : "f"(ct[3]), "f"(ct[2]));
    asm("mul.rn.f16x2 %0, %1, %2;" : "=r"(p0) : "r"(p0), "r"(cexh2));
    asm("mul.rn.f16x2 %0, %1, %2;" : "=r"(p1) : "r"(p1), "r"(cexh2));
    asm("ex2.approx.f16x2 %0, %1;" : "=r"(p0) : "r"(p0));
    asm("ex2.approx.f16x2 %0, %1;" : "=r"(p1) : "r"(p1));
    asm("add.rn.f16x2 %0, %1, %2;" : "=r"(hacc[mi * 2])     : "r"(hacc[mi * 2]),     "r"(p0));
    asm("add.rn.f16x2 %0, %1, %2;" : "=r"(hacc[mi * 2 + 1]) : "r"(hacc[mi * 2 + 1]), "r"(p1));
}

// ---------------------------------------------------------------------------
// K0: Wt transpose/convert + slot softmax (merged)
// ---------------------------------------------------------------------------
__global__ void prep_kernel(const float* __restrict__ Wq, const float* __restrict__ Wk,
                            const float* __restrict__ logits) {
    if (blockIdx.x < 128) {
        int idx = blockIdx.x * 256 + threadIdx.x;
        int q = idx >> 8, d = idx & 255;
        g_Wt[0][q * Ddim + d] = __float2half(Wq[d * QKdim + q]);
        g_Wt[1][q * Ddim + d] = __float2half(Wk[d * QKdim + q]);
        return;
    }
    int m = blockIdx.x - 128;
    int tid = threadIdx.x;
    __shared__ float sred[256];
    const float* row = logits + m * Ndim;

    float mx = -1e30f;
    for (int n = tid; n < Ndim; n += 256) mx = fmaxf(mx, row[n]);
    sred[tid] = mx; __syncthreads();
    for (int s = 128; s > 0; s >>= 1) { if (tid < s) sred[tid] = fmaxf(sred[tid], sred[tid + s]); __syncthreads(); }
    mx = sred[0]; __syncthreads();

    float sum = 0.f;
    for (int n = tid; n < Ndim; n += 256) sum += __expf(row[n] - mx);
    sred[tid] = sum; __syncthreads();
    for (int s = 128; s > 0; s >>= 1) { if (tid < s) sred[tid] += sred[tid + s]; __syncthreads(); }
    float inv = 1.0f / sred[0];

    for (int n = tid; n < Ndim; n += 256)
        g_slotw[m * Ndim + n] = __expf(row[n] - mx) * inv;
}

// ---------------------------------------------------------------------------
// K1: projection GEMM (f16 compute, e4m3 output), register-prefetched
// ---------------------------------------------------------------------------
#define PLDA 40

__global__ __launch_bounds__(256) void proj_kernel(const float* __restrict__ H0,
                                                   const float* __restrict__ X0) {
    const int z = blockIdx.y;
    const float* A = z ? X0 : H0;
    const __half* W = g_Wt[z];
    unsigned char* Out = z ? g_K8 : g_Q8;
    const int row0 = blockIdx.x * 128;

    __shared__ __half As[128 * PLDA];
    __shared__ __half Bs[128 * PLDA];

    const int tid = threadIdx.x;
    const int wid = tid >> 5, lane = tid & 31;
    const int warp_m = wid >> 2, warp_n = wid & 3;
    const int q = lane >> 2, r = lane & 3;

    float c[4][4][4];
#pragma unroll
    for (int mi = 0; mi < 4; mi++)
#pragma unroll
        for (int ni = 0; ni < 4; ni++)
#pragma unroll
            for (int j = 0; j < 4; j++) c[mi][ni][j] = 0.f;

    const int arow = tid >> 3, ac4 = tid & 7;
    const int brow0 = tid >> 4, bcc = tid & 15;

    float4 av[4];
    uint32_t bv[8];
#pragma unroll
    for (int i = 0; i < 4; i++)
        av[i] = *(const float4*)&A[(size_t)(row0 + arow + i * 32) * Ddim + ac4 * 4];
#pragma unroll
    for (int i = 0; i < 8; i++)
        bv[i] = *(const uint32_t*)&W[(brow0 + i * 16) * Ddim + bcc * 2];

    for (int k0 = 0; k0 < Ddim; k0 += 32) {
        __syncthreads();
#pragma unroll
        for (int i = 0; i < 4; i++) {
            __half2 p0, p1;
            p0.x = __float2half(av[i].x); p0.y = __float2half(av[i].y);
            p1.x = __float2half(av[i].z); p1.y = __float2half(av[i].w);
            *(__half2*)&As[(arow + i * 32) * PLDA + ac4 * 4]     = p0;
            *(__half2*)&As[(arow + i * 32) * PLDA + ac4 * 4 + 2] = p1;
        }
#pragma unroll
        for (int i = 0; i < 8; i++)
            *(uint32_t*)&Bs[(brow0 + i * 16) * PLDA + bcc * 2] = bv[i];
        __syncthreads();

        if (k0 + 32 < Ddim) {
#pragma unroll
            for (int i = 0; i < 4; i++)
                av[i] = *(const float4*)&A[(size_t)(row0 + arow + i * 32) * Ddim + k0 + 32 + ac4 * 4];
#pragma unroll
            for (int i = 0; i < 8; i++)
                bv[i] = *(const uint32_t*)&W[(brow0 + i * 16) * Ddim + k0 + 32 + bcc * 2];
        }

#pragma unroll
        for (int ks = 0; ks < 32; ks += 16) {
            uint32_t af[4][4], bfg[4][2];
#pragma unroll
            for (int mi = 0; mi < 4; mi++) {
                const __half* p = &As[(warp_m * 64 + mi * 16 + q) * PLDA + ks + 2 * r];
                af[mi][0] = *(const uint32_t*)p;
                af[mi][1] = *(const uint32_t*)(p + 8 * PLDA);
                af[mi][2] = *(const uint32_t*)(p + 8);
                af[mi][3] = *(const uint32_t*)(p + 8 * PLDA + 8);
            }
#pragma unroll
            for (int ni = 0; ni < 4; ni++) {
                const __half* p = &Bs[(warp_n * 32 + ni * 8 + q) * PLDA + ks + 2 * r];
                bfg[ni][0] = *(const uint32_t*)p;
                bfg[ni][1] = *(const uint32_t*)(p + 8);
            }
#pragma unroll
            for (int mi = 0; mi < 4; mi++)
#pragma unroll
                for (int ni = 0; ni < 4; ni++)
                    mma_f16(c[mi][ni], af[mi], bfg[ni]);
        }
    }

#pragma unroll
    for (int mi = 0; mi < 4; mi++) {
        int row = row0 + warp_m * 64 + mi * 16 + q;
#pragma unroll
        for (int ni = 0; ni < 4; ni++) {
            int col = warp_n * 32 + ni * 8 + 2 * r;
            *(uint16_t*)&Out[(size_t)row * QKdim + col] =
                cvt_e4m3x2(c[mi][ni][1], c[mi][ni][0]);
            *(uint16_t*)&Out[(size_t)(row + 8) * QKdim + col] =
                cvt_e4m3x2(c[mi][ni][3], c[mi][ni][2]);
        }
    }
}

// ---------------------------------------------------------------------------
// K2: sumexp via fp8 MMA, 3-stage ring, phase-split exp interleave.
// ---------------------------------------------------------------------------
#define CEX   (0.08838834764831845f * 1.4426950408889634f)   // 128^-0.5 * log2(e)
#define KLD8  144
#define TILE8 (128 * KLD8)          // 18432

extern __shared__ char s_dyn[];

__device__ __forceinline__ void stage128_8(uint32_t sdst, const unsigned char* g, int tid) {
#pragma unroll
    for (int i = 0; i < 4; i++) {
        int lin = tid + i * 256;
        int row = lin >> 3, cc = lin & 7;
        CP_ASYNC16(sdst + row * KLD8 + cc * 16, g + row * 128 + cc * 16);
    }
}

__global__ __launch_bounds__(256, 2) void sumexp_kernel() {
    const uint32_t sb = smem_u32(s_dyn);
    const uint32_t sQ = sb;
    uint32_t bcur = sb + TILE8, bnext = sb + 2 * TILE8, bstage = sb + 3 * TILE8;
    __shared__ float red[128];

    const int n0 = blockIdx.x * 128;
    const int b = blockIdx.y;
    const int tid = threadIdx.x;
    const int wid = tid >> 5, lane = tid & 31;
    const int warp_m = wid >> 2, warp_n = wid & 3;
    const int q = lane >> 2, r = lane & 3;

    const unsigned char* Qg = g_Q8 + ((size_t)(b * Ndim) + n0) * QKdim;
    const unsigned char* Kg = g_K8 + (size_t)(b * Ndim) * QKdim;

    // prologue: group0 = Q + chunk0, group1 = chunk1
    stage128_8(sQ, Qg, tid);
    stage128_8(bcur, Kg, tid);
    CP_COMMIT();
    stage128_8(bnext, Kg + 128 * 128, tid);
    CP_COMMIT();

    const int arow = warp_m * 64 + ((lane >> 3) & 1) * 8 + (lane & 7);
    const uint32_t acol = (lane >> 4) * 16;
    uint32_t aaddr[4];
#pragma unroll
    for (int mi = 0; mi < 4; mi++) aaddr[mi] = sQ + (arow + mi * 16) * KLD8 + acol;
    const int brow = warp_n * 32 + ((lane >> 4) & 1) * 8 + (lane & 7);
    const uint32_t boff = brow * KLD8 + ((lane >> 3) & 1) * 16;

    const __half2 cexh = __float2half2_rn(CEX);
    const uint32_t cexh2 = *(const uint32_t*)&cexh;

    float rs[8];
    uint32_t hacc[8];
#pragma unroll
    for (int i = 0; i < 8; i++) { rs[i] = 0.f; hacc[i] = 0u; }

    for (int j = 0; j < 32; j++) {
        CP_WAIT1();                // chunk j (and Q, for j=0) landed
        __syncthreads();           // visible to all; bstage consumed by all
        if (j + 2 < 32)
            stage128_8(bstage, Kg + (size_t)(j + 2) * 128 * 128, tid);
        CP_COMMIT();

        const uint32_t kbase = bcur + boff;
        float c[4][4][4];

        // phase A: ni 0,1 (B group 0)
#pragma unroll
        for (int kk = 0; kk < 4; kk++) {
            const uint32_t ko = kk * 32;
            uint32_t af[4][4], bq[4];
            ldsm_x4(bq, kbase + ko);
#pragma unroll
            for (int mi = 0; mi < 4; mi++) ldsm_x4(af[mi], aaddr[mi] + ko);
#pragma unroll
            for (int mi = 0; mi < 4; mi++) {
                if (kk == 0) {
#pragma unroll
                    for (int ni = 0; ni < 2; ni++)
#pragma unroll
                        for (int jj = 0; jj < 4; jj++) c[mi][ni][jj] = 0.f;
                }
                mma_fp8(c[mi][0], af[mi], &bq[0]);
                mma_fp8(c[mi][1], af[mi], &bq[2]);
            }
        }
        // phase B: ni 2,3 MMAs with phase-A exp drains interleaved
#pragma unroll
        for (int kk = 0; kk < 4; kk++) {
            const uint32_t ko = kk * 32;
            uint32_t af[4][4], bq[4];
            ldsm_x4(bq, kbase + 16 * KLD8 + ko);
#pragma unroll
            for (int mi = 0; mi < 4; mi++) ldsm_x4(af[mi], aaddr[mi] + ko);
#pragma unroll
            for (int mi = 0; mi < 4; mi++) {
                if (kk == 0) {
#pragma unroll
                    for (int ni = 2; ni < 4; ni++)
#pragma unroll
                        for (int jj = 0; jj < 4; jj++) c[mi][ni][jj] = 0.f;
                }
                mma_fp8(c[mi][2], af[mi], &bq[0]);
                mma_fp8(c[mi][3], af[mi], &bq[2]);
            }
            // drain 2 phase-A tiles per kk (all 8 across the 4 iterations)
            drain_tile(c[kk][0], hacc, kk, cexh2);
            drain_tile(c[kk][1], hacc, kk, cexh2);
        }
        // phase C: drain phase-B tiles
#pragma unroll
        for (int mi = 0; mi < 4; mi++) {
            drain_tile(c[mi][2], hacc, mi, cexh2);
            drain_tile(c[mi][3], hacc, mi, cexh2);
        }
        // fold h2 accumulators into f32 (per chunk: values small, f16-safe)
#pragma unroll
        for (int i = 0; i < 8; i++) {
            float2 f = __half22float2(*(__half2*)&hacc[i]);
            rs[i] += f.x + f.y;
            hacc[i] = 0u;
        }

        // rotate ring
        uint32_t t = bcur; bcur = bnext; bnext = bstage; bstage = t;
    }

    // reduce across lanes sharing each row (lane & 3)
#pragma unroll
    for (int i = 0; i < 8; i++) {
        rs[i] += __shfl_xor_sync(0xffffffffu, rs[i], 1);
        rs[i] += __shfl_xor_sync(0xffffffffu, rs[i], 2);
    }
    if (tid < 128) red[tid] = 0.f;
    __syncthreads();
    if (r == 0) {
#pragma unroll
        for (int mi = 0; mi < 4; mi++) {
            atomicAdd(&red[warp_m * 64 + mi * 16 + q],     rs[mi * 2]);
            atomicAdd(&red[warp_m * 64 + mi * 16 + q + 8], rs[mi * 2 + 1]);
        }
    }
    __syncthreads();
    if (tid < 128) g_sumexp[b * Ndim + n0 + tid] = red[tid];
    __syncthreads();
    for (int s = 64; s > 0; s >>= 1) {
        if (tid < s) red[tid] += red[tid + s];
        __syncthreads();
    }
    if (tid == 0) g_tsum[b * 32 + blockIdx.x] = red[0];
}

// ---------------------------------------------------------------------------
// K3: partial out accumulation, 64-row chunks (grid 64 x 8) + coef sums
// ---------------------------------------------------------------------------
__global__ __launch_bounds__(256) void out_accum_kernel(const float* __restrict__ H0) {
    const int nc = blockIdx.x, b = blockIdx.y;
    const int n0 = nc * 64;
    const int tid = threadIdx.x;
    __shared__ float coefT[64 * 32];
    __shared__ float sgrp[8 * 32];

#pragma unroll
    for (int i = 0; i < 8; i++) {
        int lin = tid + i * 256;
        int n = lin >> 5, m = lin & 31;
        coefT[n * 32 + m] = g_slotw[m * Ndim + n0 + n] * g_sumexp[b * Ndim + n0 + n];
    }
    __syncthreads();

    {
        const int m = tid & 31, g = tid >> 5;
        float s = 0.f;
#pragma unroll
        for (int j = 0; j < 8; j++) s += coefT[(g + j * 8) * 32 + m];
        sgrp[g * 32 + m] = s;
    }
    __syncthreads();
    if (tid < 32) {
        float s = 0.f;
#pragma unroll
        for (int g = 0; g < 8; g++) s += sgrp[g * 32 + tid];
        g_csum[(b * 64 + nc) * 32 + tid] = s;
    }

    float acc[32];
#pragma unroll
    for (int m = 0; m < 32; m++) acc[m] = 0.f;

    const float* H = H0 + ((size_t)b * Ndim + n0) * Ddim + tid;
#pragma unroll 4
    for (int n = 0; n < 64; n++) {
        float h = H[(size_t)n * Ddim];
        const float4* cp = (const float4*)&coefT[n * 32];
#pragma unroll
        for (int j = 0; j < 8; j++) {
            float4 c4 = cp[j];
            acc[j * 4 + 0] = fmaf(c4.x, h, acc[j * 4 + 0]);
            acc[j * 4 + 1] = fmaf(c4.y, h, acc[j * 4 + 1]);
            acc[j * 4 + 2] = fmaf(c4.z, h, acc[j * 4 + 2]);
            acc[j * 4 + 3] = fmaf(c4.w, h, acc[j * 4 + 3]);
        }
    }

    float* dst = &g_part[(((size_t)b * 64 + nc) * Mdim) * Ddim + tid];
#pragma unroll
    for (int m = 0; m < 32; m++) dst[(size_t)m * Ddim] = acc[m];
}

// ---------------------------------------------------------------------------
// K4: reduce partials + inline norm + divide.  grid 256 = (b,m), 256 thr = d.
// ---------------------------------------------------------------------------
__global__ void reduce_out_kernel(float* __restrict__ out) {
    const int bm = blockIdx.x;
    const int b = bm >> 5, m = bm & 31;
    const int d = threadIdx.x;
    __shared__ float snorm;

    if (d == 0) {
        float T = 0.f;
#pragma unroll
        for (int t = 0; t < 32; t++) T += g_tsum[b * 32 + t];
        float s = 0.f;
#pragma unroll
        for (int nc = 0; nc < 64; nc++) s += g_csum[(b * 64 + nc) * 32 + m];
        snorm = s + 1e-6f * T;
    }
    float s = 0.f;
#pragma unroll 8
    for (int nc = 0; nc < 64; nc++)
        s += g_part[(((size_t)b * 64 + nc) * Mdim + m) * Ddim + d];
    __syncthreads();
    out[(bm << 8) + d] = s / snorm;
}

// ---------------------------------------------------------------------------
// launch
// ---------------------------------------------------------------------------
extern "C" void kernel_launch(void* const* d_in, const int* in_sizes, int n_in,
                              void* d_out, int out_size) {
    const float* X0   = (const float*)d_in[0];
    const float* H0   = (const float*)d_in[1];
    const float* Wq   = (const float*)d_in[2];
    const float* Wk   = (const float*)d_in[3];
    const float* slot = (const float*)d_in[4];
    float* out = (float*)d_out;

    const int SMEM_S = 4 * TILE8;   // 73728
    cudaFuncSetAttribute(sumexp_kernel, cudaFuncAttributeMaxDynamicSharedMemorySize, SMEM_S);

    prep_kernel<<<160, 256>>>(Wq, Wk, slot);
    proj_kernel<<<dim3(256, 2), 256>>>(H0, X0);
    sumexp_kernel<<<dim3(32, 8), 256, SMEM_S>>>();
    out_accum_kernel<<<dim3(64, 8), 256>>>(H0);
    reduce_out_kernel<<<256, 256>>>(out);
    (void)in_sizes; (void)n_in; (void)out_size;
}

// round 8
// speedup vs baseline: 1.1934x; 1.1934x over previous
#include <cuda_runtime.h>
#include <cuda_fp16.h>
#include <cstdint>

// ============================================================================
// B=8, N=4096, D=256, QK=128, M=32
//   Q = H0 @ Wq ; K = X0 @ Wk                       (f16 GEMM)
//   sumexp[b,n] = sum_m exp(scale * Q[b,n,:]·K[b,m,:])   (f16 MMA, proven R3)
//   out[b,m,:] = (sum_n coef[b,m,n]*H0[b,n,:]) / (sum_n coef[b,m,n] + 1e-6*T[b])
//     where coef = slotw * sumexp  (f16), T[b] = sum_n sumexp[b,n]
// R8 = R7 with outgemm moved to dynamic smem (static 48KB limit hit).
// ============================================================================

#define Bdim 8
#define Ndim 4096
#define Ddim 256
#define QKdim 128
#define Mdim 32

__device__ __half g_Qh[Bdim * Ndim * QKdim];          // 8 MB
__device__ __half g_Kh[Bdim * Ndim * QKdim];          // 8 MB
__device__ __half g_Wt[2][QKdim * Ddim];
__device__ float g_sumexp[Bdim * Ndim];
__device__ float g_tsum[Bdim * 32];                   // per n-tile sumexp totals
__device__ float g_slotw[Mdim * Ndim];
__device__ float g_csum[Bdim * 16 * Mdim];            // per-chunk coef sums
__device__ float g_part[Bdim * 16 * Mdim * Ddim];     // 4 MB partials

// ---------------------------------------------------------------------------
// helpers
// ---------------------------------------------------------------------------
__device__ __forceinline__ uint32_t smem_u32(const void* p) {
    uint32_t a;
    asm("{ .reg .u64 t; cvta.to.shared.u64 t, %1; cvt.u32.u64 %0, t; }" : "=r"(a) : "l"(p));
    return a;
}
__device__ __forceinline__ float ex2f(float x) {
    float r; asm("ex2.approx.ftz.f32 %0, %1;" : "=f"(r) : "f"(x)); return r;
}
#define CP_ASYNC16(dst, src) \
    asm volatile("cp.async.cg.shared.global [%0], [%1], 16;" :: "r"(dst), "l"(src))
#define CP_COMMIT() asm volatile("cp.async.commit_group;" ::: "memory")
#define CP_WAIT1()  asm volatile("cp.async.wait_group 1;" ::: "memory")

__device__ __forceinline__ void ldsm_x4(uint32_t* r, uint32_t addr) {
    asm volatile("ldmatrix.sync.aligned.m8n8.x4.shared.b16 {%0,%1,%2,%3}, [%4];"
                 : "=r"(r[0]), "=r"(r[1]), "=r"(r[2]), "=r"(r[3]) : "r"(addr));
}
__device__ __forceinline__ void ldsm_x4_trans(uint32_t* r, uint32_t addr) {
    asm volatile("ldmatrix.sync.aligned.m8n8.x4.trans.shared.b16 {%0,%1,%2,%3}, [%4];"
                 : "=r"(r[0]), "=r"(r[1]), "=r"(r[2]), "=r"(r[3]) : "r"(addr));
}
__device__ __forceinline__ void mma_f16(float* c, const uint32_t* a, const uint32_t* b) {
    asm volatile(
        "mma.sync.aligned.m16n8k16.row.col.f32.f16.f16.f32 "
        "{%0,%1,%2,%3}, {%4,%5,%6,%7}, {%8,%9}, {%0,%1,%2,%3};"
        : "+f"(c[0]), "+f"(c[1]), "+f"(c[2]), "+f"(c[3])
        : "r"(a[0]), "r"(a[1]), "r"(a[2]), "r"(a[3]), "r"(b[0]), "r"(b[1]));
}

extern __shared__ char s_dyn[];

// ---------------------------------------------------------------------------
// K0: Wt transpose/convert + slot softmax (merged)
// ---------------------------------------------------------------------------
__global__ void prep_kernel(const float* __restrict__ Wq, const float* __restrict__ Wk,
                            const float* __restrict__ logits) {
    if (blockIdx.x < 128) {
        int idx = blockIdx.x * 256 + threadIdx.x;
        int q = idx >> 8, d = idx & 255;
        g_Wt[0][q * Ddim + d] = __float2half(Wq[d * QKdim + q]);
        g_Wt[1][q * Ddim + d] = __float2half(Wk[d * QKdim + q]);
        return;
    }
    int m = blockIdx.x - 128;
    int tid = threadIdx.x;
    __shared__ float sred[256];
    const float* row = logits + m * Ndim;

    float mx = -1e30f;
    for (int n = tid; n < Ndim; n += 256) mx = fmaxf(mx, row[n]);
    sred[tid] = mx; __syncthreads();
    for (int s = 128; s > 0; s >>= 1) { if (tid < s) sred[tid] = fmaxf(sred[tid], sred[tid + s]); __syncthreads(); }
    mx = sred[0]; __syncthreads();

    float sum = 0.f;
    for (int n = tid; n < Ndim; n += 256) sum += __expf(row[n] - mx);
    sred[tid] = sum; __syncthreads();
    for (int s = 128; s > 0; s >>= 1) { if (tid < s) sred[tid] += sred[tid + s]; __syncthreads(); }
    float inv = 1.0f / sred[0];

    for (int n = tid; n < Ndim; n += 256)
        g_slotw[m * Ndim + n] = __expf(row[n] - mx) * inv;
}

// ---------------------------------------------------------------------------
// K1: projection GEMM (f16), register-prefetched (proven)
// ---------------------------------------------------------------------------
#define PLDA 40

__global__ __launch_bounds__(256) void proj_kernel(const float* __restrict__ H0,
                                                   const float* __restrict__ X0) {
    const int z = blockIdx.y;
    const float* A = z ? X0 : H0;
    const __half* W = g_Wt[z];
    __half* Out = z ? g_Kh : g_Qh;
    const int row0 = blockIdx.x * 128;

    __shared__ __half As[128 * PLDA];
    __shared__ __half Bs[128 * PLDA];

    const int tid = threadIdx.x;
    const int wid = tid >> 5, lane = tid & 31;
    const int warp_m = wid >> 2, warp_n = wid & 3;
    const int q = lane >> 2, r = lane & 3;

    float c[4][4][4];
#pragma unroll
    for (int mi = 0; mi < 4; mi++)
#pragma unroll
        for (int ni = 0; ni < 4; ni++)
#pragma unroll
            for (int j = 0; j < 4; j++) c[mi][ni][j] = 0.f;

    const int arow = tid >> 3, ac4 = tid & 7;
    const int brow0 = tid >> 4, bcc = tid & 15;

    float4 av[4];
    uint32_t bv[8];
#pragma unroll
    for (int i = 0; i < 4; i++)
        av[i] = *(const float4*)&A[(size_t)(row0 + arow + i * 32) * Ddim + ac4 * 4];
#pragma unroll
    for (int i = 0; i < 8; i++)
        bv[i] = *(const uint32_t*)&W[(brow0 + i * 16) * Ddim + bcc * 2];

    for (int k0 = 0; k0 < Ddim; k0 += 32) {
        __syncthreads();
#pragma unroll
        for (int i = 0; i < 4; i++) {
            __half2 p0, p1;
            p0.x = __float2half(av[i].x); p0.y = __float2half(av[i].y);
            p1.x = __float2half(av[i].z); p1.y = __float2half(av[i].w);
            *(__half2*)&As[(arow + i * 32) * PLDA + ac4 * 4]     = p0;
            *(__half2*)&As[(arow + i * 32) * PLDA + ac4 * 4 + 2] = p1;
        }
#pragma unroll
        for (int i = 0; i < 8; i++)
            *(uint32_t*)&Bs[(brow0 + i * 16) * PLDA + bcc * 2] = bv[i];
        __syncthreads();

        if (k0 + 32 < Ddim) {
#pragma unroll
            for (int i = 0; i < 4; i++)
                av[i] = *(const float4*)&A[(size_t)(row0 + arow + i * 32) * Ddim + k0 + 32 + ac4 * 4];
#pragma unroll
            for (int i = 0; i < 8; i++)
                bv[i] = *(const uint32_t*)&W[(brow0 + i * 16) * Ddim + k0 + 32 + bcc * 2];
        }

#pragma unroll
        for (int ks = 0; ks < 32; ks += 16) {
            uint32_t af[4][4], bfg[4][2];
#pragma unroll
            for (int mi = 0; mi < 4; mi++) {
                const __half* p = &As[(warp_m * 64 + mi * 16 + q) * PLDA + ks + 2 * r];
                af[mi][0] = *(const uint32_t*)p;
                af[mi][1] = *(const uint32_t*)(p + 8 * PLDA);
                af[mi][2] = *(const uint32_t*)(p + 8);
                af[mi][3] = *(const uint32_t*)(p + 8 * PLDA + 8);
            }
#pragma unroll
            for (int ni = 0; ni < 4; ni++) {
                const __half* p = &Bs[(warp_n * 32 + ni * 8 + q) * PLDA + ks + 2 * r];
                bfg[ni][0] = *(const uint32_t*)p;
                bfg[ni][1] = *(const uint32_t*)(p + 8);
            }
#pragma unroll
            for (int mi = 0; mi < 4; mi++)
#pragma unroll
                for (int ni = 0; ni < 4; ni++)
                    mma_f16(c[mi][ni], af[mi], bfg[ni]);
        }
    }

#pragma unroll
    for (int mi = 0; mi < 4; mi++) {
        int row = row0 + warp_m * 64 + mi * 16 + q;
#pragma unroll
        for (int ni = 0; ni < 4; ni++) {
            int col = warp_n * 32 + ni * 8 + 2 * r;
            __half2 v0, v1;
            v0.x = __float2half(c[mi][ni][0]); v0.y = __float2half(c[mi][ni][1]);
            v1.x = __float2half(c[mi][ni][2]); v1.y = __float2half(c[mi][ni][3]);
            *(__half2*)&Out[(size_t)row * QKdim + col]        = v0;
            *(__half2*)&Out[(size_t)(row + 8) * QKdim + col]  = v1;
        }
    }
}

// ---------------------------------------------------------------------------
// K2: sumexp — proven R3 loop (f16) + T-tile tail.
// ---------------------------------------------------------------------------
#define CEX   (0.08838834764831845f * 1.4426950408889634f)   // 128^-0.5 * log2(e)
#define KLDB  272
#define TILEB (128 * KLDB)

__device__ __forceinline__ void stage128(uint32_t sdst, const __half* g, int tid) {
#pragma unroll
    for (int i = 0; i < 8; i++) {
        int lin = tid + i * 256;
        int row = lin >> 4, cc = lin & 15;
        CP_ASYNC16(sdst + row * KLDB + cc * 16, g + row * 128 + cc * 8);
    }
}

__global__ __launch_bounds__(256, 2) void sumexp_kernel() {
    const uint32_t sb = smem_u32(s_dyn);
    const uint32_t sQ = sb, sK0 = sb + TILEB, sK1 = sb + 2 * TILEB;
    __shared__ float red[128];

    const int n0 = blockIdx.x * 128;
    const int b = blockIdx.y;
    const int tid = threadIdx.x;
    const int wid = tid >> 5, lane = tid & 31;
    const int warp_m = wid >> 2, warp_n = wid & 3;
    const int q = lane >> 2, r = lane & 3;

    const __half* Qg = g_Qh + ((size_t)(b * Ndim) + n0) * QKdim;
    const __half* Kg = g_Kh + (size_t)(b * Ndim) * QKdim;

    stage128(sQ, Qg, tid);
    stage128(sK0, Kg, tid);
    CP_COMMIT();
    stage128(sK1, Kg + 128 * 128, tid);
    CP_COMMIT();
    CP_WAIT1();
    __syncthreads();

    const int arow = warp_m * 64 + ((lane >> 3) & 1) * 8 + (lane & 7);
    const uint32_t acol = (lane >> 4) * 16;
    uint32_t aaddr[4];
#pragma unroll
    for (int mi = 0; mi < 4; mi++) aaddr[mi] = sQ + (arow + mi * 16) * KLDB + acol;
    const int brow = warp_n * 32 + ((lane >> 4) & 1) * 8 + (lane & 7);
    const uint32_t boff = brow * KLDB + ((lane >> 3) & 1) * 16;

    float rs[8];
#pragma unroll
    for (int i = 0; i < 8; i++) rs[i] = 0.f;

    for (int mc = 0; mc < 32; mc++) {
        const uint32_t kbase = ((mc & 1) ? sK1 : sK0) + boff;

        float c[4][4][4];
#pragma unroll
        for (int mi = 0; mi < 4; mi++)
#pragma unroll
            for (int ni = 0; ni < 4; ni++)
#pragma unroll
                for (int j = 0; j < 4; j++) c[mi][ni][j] = 0.f;

#pragma unroll
        for (int kk = 0; kk < 8; kk++) {
            const uint32_t ko = kk * 32;
            uint32_t af[4][4], bq[2][4];
#pragma unroll
            for (int mi = 0; mi < 4; mi++) ldsm_x4(af[mi], aaddr[mi] + ko);
#pragma unroll
            for (int np = 0; np < 2; np++) ldsm_x4(bq[np], kbase + np * 16 * KLDB + ko);
#pragma unroll
            for (int mi = 0; mi < 4; mi++)
#pragma unroll
                for (int ni = 0; ni < 4; ni++)
                    mma_f16(c[mi][ni], af[mi], &bq[ni >> 1][(ni & 1) * 2]);
        }

#pragma unroll
        for (int mi = 0; mi < 4; mi++) {
            float s0 = 0.f, s1 = 0.f;
#pragma unroll
            for (int ni = 0; ni < 4; ni++) {
                s0 += ex2f(c[mi][ni][0] * CEX) + ex2f(c[mi][ni][1] * CEX);
                s1 += ex2f(c[mi][ni][2] * CEX) + ex2f(c[mi][ni][3] * CEX);
            }
            rs[mi * 2] += s0; rs[mi * 2 + 1] += s1;
        }

        __syncthreads();
        if (mc + 2 < 32)
            stage128((mc & 1) ? sK1 : sK0, Kg + (size_t)(mc + 2) * 128 * 128, tid);
        CP_COMMIT();
        CP_WAIT1();
        __syncthreads();
    }

#pragma unroll
    for (int i = 0; i < 8; i++) {
        rs[i] += __shfl_xor_sync(0xffffffffu, rs[i], 1);
        rs[i] += __shfl_xor_sync(0xffffffffu, rs[i], 2);
    }
    if (tid < 128) red[tid] = 0.f;
    __syncthreads();
    if (r == 0) {
#pragma unroll
        for (int mi = 0; mi < 4; mi++) {
            atomicAdd(&red[warp_m * 64 + mi * 16 + q],     rs[mi * 2]);
            atomicAdd(&red[warp_m * 64 + mi * 16 + q + 8], rs[mi * 2 + 1]);
        }
    }
    __syncthreads();
    if (tid < 128) g_sumexp[b * Ndim + n0 + tid] = red[tid];
    __syncthreads();
    for (int s = 64; s > 0; s >>= 1) {
        if (tid < s) red[tid] += red[tid + s];
        __syncthreads();
    }
    if (tid == 0) g_tsum[b * 32 + blockIdx.x] = red[0];
}

// ---------------------------------------------------------------------------
// K3: out-GEMM (dynamic smem).  grid (16 kc, 8 b), 256 threads.
//   coef[32 m x 256 k] f16; Hs[64 k x 256 d] f16 double-buffered;
//   B-frags via ldmatrix.trans.  partials + csum out.
// ---------------------------------------------------------------------------
#define CA_LD 528               // coef row stride bytes (256 f16 + 8 pad)
#define HS_LD 528               // Hs row stride bytes
#define CF_BYTES (32 * CA_LD)          // 16896
#define HS_BYTES (64 * HS_LD)          // 33792
#define SMEM_O (CF_BYTES + 2 * HS_BYTES + 32 * 8 * 4)   // 85504

__global__ __launch_bounds__(256) void outgemm_kernel(const float* __restrict__ H0) {
    __half* coefA = (__half*)s_dyn;
    __half* HsBuf[2] = { (__half*)(s_dyn + CF_BYTES),
                         (__half*)(s_dyn + CF_BYTES + HS_BYTES) };
    float* csred = (float*)(s_dyn + CF_BYTES + 2 * HS_BYTES);

    const int kc = blockIdx.x, b = blockIdx.y;
    const int n0 = kc * 256;
    const int tid = threadIdx.x;
    const int wid = tid >> 5, lane = tid & 31;

    const uint32_t sCoef = smem_u32(coefA);
    const uint32_t sHs0 = smem_u32(HsBuf[0]);
    const uint32_t sHs1 = smem_u32(HsBuf[1]);

    // ---- build coef [32 m x 256 k] f16 ----
#pragma unroll
    for (int i = 0; i < 32; i++) {
        int lin = tid + i * 256;
        int m = lin >> 8, k = lin & 255;
        float v = g_slotw[m * Ndim + n0 + k] * g_sumexp[b * Ndim + n0 + k];
        coefA[m * (CA_LD / 2) + k] = __float2half(v);
    }
    __syncthreads();

    // ---- csum[m] from the SAME f16 coef (deterministic) ----
    {
        int m = tid >> 3, g = tid & 7;
        float s = 0.f;
#pragma unroll
        for (int j = 0; j < 32; j++)
            s += __half2float(coefA[m * (CA_LD / 2) + g + j * 8]);
        csred[m * 8 + g] = s;
    }
    __syncthreads();
    if (tid < 32) {
        float s = 0.f;
#pragma unroll
        for (int g = 0; g < 8; g++) s += csred[tid * 8 + g];
        g_csum[(b * 16 + kc) * 32 + tid] = s;
    }

    // ---- fragment addressing ----
    const int a_r = ((lane >> 3) & 1) * 8 + (lane & 7);
    const uint32_t a_c = (lane >> 4) * 16;
    uint32_t aad[2];
#pragma unroll
    for (int mi = 0; mi < 2; mi++)
        aad[mi] = sCoef + (mi * 16 + a_r) * CA_LD + a_c;
    const int d0 = wid * 32;                     // warp's 32-col d range
    const int b_k = ((lane >> 3) & 1) * 8 + (lane & 7);
    const uint32_t b_dofs = (lane >> 4) * 8;     // +8 d for upper half

    float c[2][4][4];
#pragma unroll
    for (int mi = 0; mi < 2; mi++)
#pragma unroll
        for (int ni = 0; ni < 4; ni++)
#pragma unroll
            for (int j = 0; j < 4; j++) c[mi][ni][j] = 0.f;

    const float* Hbase = H0 + ((size_t)b * Ndim + n0) * Ddim;

    // preload sub-chunk 0
#pragma unroll
    for (int i = 0; i < 32; i++) {
        int lin = tid + i * 256;                 // 8192 half2 = 64 n x 128
        int n = lin >> 7, dq = lin & 127;
        float2 v = *(const float2*)&Hbase[(size_t)n * Ddim + dq * 2];
        __half2 h; h.x = __float2half(v.x); h.y = __float2half(v.y);
        *(__half2*)&HsBuf[0][n * (HS_LD / 2) + dq * 2] = h;
    }
    __syncthreads();

    for (int sc = 0; sc < 4; sc++) {
        const uint32_t sH = (sc & 1) ? sHs1 : sHs0;
        if (sc + 1 < 4) {
            __half* Hn = HsBuf[(sc + 1) & 1];
            const float* Hg = Hbase + (size_t)(sc + 1) * 64 * Ddim;
#pragma unroll
            for (int i = 0; i < 32; i++) {
                int lin = tid + i * 256;
                int n = lin >> 7, dq = lin & 127;
                float2 v = *(const float2*)&Hg[(size_t)n * Ddim + dq * 2];
                __half2 h; h.x = __float2half(v.x); h.y = __float2half(v.y);
                *(__half2*)&Hn[n * (HS_LD / 2) + dq * 2] = h;
            }
        }
#pragma unroll
        for (int kk = 0; kk < 4; kk++) {
            const int kg = sc * 64 + kk * 16;
            uint32_t af[2][4], bq[2][4];
#pragma unroll
            for (int mi = 0; mi < 2; mi++) ldsm_x4(af[mi], aad[mi] + kg * 2);
#pragma unroll
            for (int np = 0; np < 2; np++)
                ldsm_x4_trans(bq[np], sH + (kk * 16 + b_k) * HS_LD
                                         + (d0 + np * 16 + b_dofs) * 2);
#pragma unroll
            for (int mi = 0; mi < 2; mi++)
#pragma unroll
                for (int ni = 0; ni < 4; ni++)
                    mma_f16(c[mi][ni], af[mi], &bq[ni >> 1][(ni & 1) * 2]);
        }
        __syncthreads();
    }

    // ---- store partial [32 m x 256 d] f32 ----
    const int q = lane >> 2, r = lane & 3;
    float* P = &g_part[((size_t)(b * 16 + kc) * Mdim) * Ddim];
#pragma unroll
    for (int mi = 0; mi < 2; mi++) {
        int row = mi * 16 + q;
#pragma unroll
        for (int ni = 0; ni < 4; ni++) {
            int col = d0 + ni * 8 + 2 * r;
            *(float2*)&P[row * Ddim + col]       = make_float2(c[mi][ni][0], c[mi][ni][1]);
            *(float2*)&P[(row + 8) * Ddim + col] = make_float2(c[mi][ni][2], c[mi][ni][3]);
        }
    }
}

// ---------------------------------------------------------------------------
// K4: reduce partials + divisor + divide.  grid 256 = (b,m), 256 thr = d.
// ---------------------------------------------------------------------------
__global__ void reduce_out_kernel(float* __restrict__ out) {
    const int bm = blockIdx.x;
    const int b = bm >> 5, m = bm & 31;
    const int d = threadIdx.x;
    __shared__ float snorm;

    if (d == 0) {
        float T = 0.f;
#pragma unroll
        for (int t = 0; t < 32; t++) T += g_tsum[b * 32 + t];
        float s = 0.f;
#pragma unroll
        for (int kc = 0; kc < 16; kc++) s += g_csum[(b * 16 + kc) * 32 + m];
        snorm = s + 1e-6f * T;
    }
    float s = 0.f;
#pragma unroll
    for (int kc = 0; kc < 16; kc++)
        s += g_part[((size_t)(b * 16 + kc) * Mdim + m) * Ddim + d];
    __syncthreads();
    out[(bm << 8) + d] = s / snorm;
}

// ---------------------------------------------------------------------------
// launch
// ---------------------------------------------------------------------------
extern "C" void kernel_launch(void* const* d_in, const int* in_sizes, int n_in,
                              void* d_out, int out_size) {
    const float* X0   = (const float*)d_in[0];
    const float* H0   = (const float*)d_in[1];
    const float* Wq   = (const float*)d_in[2];
    const float* Wk   = (const float*)d_in[3];
    const float* slot = (const float*)d_in[4];
    float* out = (float*)d_out;

    const int SMEM_S = 3 * TILEB;   // 104448
    cudaFuncSetAttribute(sumexp_kernel, cudaFuncAttributeMaxDynamicSharedMemorySize, SMEM_S);
    cudaFuncSetAttribute(outgemm_kernel, cudaFuncAttributeMaxDynamicSharedMemorySize, SMEM_O);

    prep_kernel<<<160, 256>>>(Wq, Wk, slot);
    proj_kernel<<<dim3(256, 2), 256>>>(H0, X0);
    sumexp_kernel<<<dim3(32, 8), 256, SMEM_S>>>();
    outgemm_kernel<<<dim3(16, 8), 256, SMEM_O>>>(H0);
    reduce_out_kernel<<<256, 256>>>(out);
    (void)in_sizes; (void)n_in; (void)out_size;
}

// round 9
// speedup vs baseline: 1.2500x; 1.0474x over previous
#include <cuda_runtime.h>
#include <cuda_fp16.h>
#include <cstdint>

// ============================================================================
// B=8, N=4096, D=256, QK=128, M=32
//   Q = H0 @ Wq ; K = X0 @ Wk                       (f16 GEMM)
//   sumexp[b,n] = sum_m exp(scale * Q[b,n,:]·K[b,m,:])   (f16 MMA)
//   out[b,m,:] = (sum_n coef*H0) / (sum_n coef + 1e-6*T[b]),  coef=slotw*sumexp
// R9: sumexp warp-quad split — two independent 4-warp groups per CTA, each
//     owning half the K rows with private double buffers + named barriers,
//     so exp(MUFU) of one quad overlaps MMA(tensor) of the other.
//     outgemm regridded (n-chunk 128, occ 2, full chip).
// ============================================================================

#define Bdim 8
#define Ndim 4096
#define Ddim 256
#define QKdim 128
#define Mdim 32

__device__ __half g_Qh[Bdim * Ndim * QKdim];
__device__ __half g_Kh[Bdim * Ndim * QKdim];
__device__ __half g_Wt[2][QKdim * Ddim];
__device__ float g_sumexp[Bdim * Ndim];
__device__ float g_tsum[Bdim * 32];
__device__ float g_slotw[Mdim * Ndim];
__device__ float g_csum[Bdim * 32 * Mdim];
__device__ float g_part[Bdim * 32 * Mdim * Ddim];     // 8 MB partials

// ---------------------------------------------------------------------------
// helpers
// ---------------------------------------------------------------------------
__device__ __forceinline__ uint32_t smem_u32(const void* p) {
    uint32_t a;
    asm("{ .reg .u64 t; cvta.to.shared.u64 t, %1; cvt.u32.u64 %0, t; }" : "=r"(a) : "l"(p));
    return a;
}
__device__ __forceinline__ float ex2f(float x) {
    float r; asm("ex2.approx.ftz.f32 %0, %1;" : "=f"(r) : "f"(x)); return r;
}
#define CP_ASYNC16(dst, src) \
    asm volatile("cp.async.cg.shared.global [%0], [%1], 16;" :: "r"(dst), "l"(src))
#define CP_COMMIT() asm volatile("cp.async.commit_group;" ::: "memory")
#define CP_WAIT1()  asm volatile("cp.async.wait_group 1;" ::: "memory")
#define BAR_QUAD(id) asm volatile("bar.sync %0, 128;" :: "r"(id) : "memory")

__device__ __forceinline__ void ldsm_x4(uint32_t* r, uint32_t addr) {
    asm volatile("ldmatrix.sync.aligned.m8n8.x4.shared.b16 {%0,%1,%2,%3}, [%4];"
                 : "=r"(r[0]), "=r"(r[1]), "=r"(r[2]), "=r"(r[3]) : "r"(addr));
}
__device__ __forceinline__ void ldsm_x4_trans(uint32_t* r, uint32_t addr) {
    asm volatile("ldmatrix.sync.aligned.m8n8.x4.trans.shared.b16 {%0,%1,%2,%3}, [%4];"
                 : "=r"(r[0]), "=r"(r[1]), "=r"(r[2]), "=r"(r[3]) : "r"(addr));
}
__device__ __forceinline__ void mma_f16(float* c, const uint32_t* a, const uint32_t* b) {
    asm volatile(
        "mma.sync.aligned.m16n8k16.row.col.f32.f16.f16.f32 "
        "{%0,%1,%2,%3}, {%4,%5,%6,%7}, {%8,%9}, {%0,%1,%2,%3};"
        : "+f"(c[0]), "+f"(c[1]), "+f"(c[2]), "+f"(c[3])
        : "r"(a[0]), "r"(a[1]), "r"(a[2]), "r"(a[3]), "r"(b[0]), "r"(b[1]));
}

extern __shared__ char s_dyn[];

// ---------------------------------------------------------------------------
// K0: Wt transpose/convert + slot softmax (merged)
// ---------------------------------------------------------------------------
__global__ void prep_kernel(const float* __restrict__ Wq, const float* __restrict__ Wk,
                            const float* __restrict__ logits) {
    if (blockIdx.x < 128) {
        int idx = blockIdx.x * 256 + threadIdx.x;
        int q = idx >> 8, d = idx & 255;
        g_Wt[0][q * Ddim + d] = __float2half(Wq[d * QKdim + q]);
        g_Wt[1][q * Ddim + d] = __float2half(Wk[d * QKdim + q]);
        return;
    }
    int m = blockIdx.x - 128;
    int tid = threadIdx.x;
    __shared__ float sred[256];
    const float* row = logits + m * Ndim;

    float mx = -1e30f;
    for (int n = tid; n < Ndim; n += 256) mx = fmaxf(mx, row[n]);
    sred[tid] = mx; __syncthreads();
    for (int s = 128; s > 0; s >>= 1) { if (tid < s) sred[tid] = fmaxf(sred[tid], sred[tid + s]); __syncthreads(); }
    mx = sred[0]; __syncthreads();

    float sum = 0.f;
    for (int n = tid; n < Ndim; n += 256) sum += __expf(row[n] - mx);
    sred[tid] = sum; __syncthreads();
    for (int s = 128; s > 0; s >>= 1) { if (tid < s) sred[tid] += sred[tid + s]; __syncthreads(); }
    float inv = 1.0f / sred[0];

    for (int n = tid; n < Ndim; n += 256)
        g_slotw[m * Ndim + n] = __expf(row[n] - mx) * inv;
}

// ---------------------------------------------------------------------------
// K1: projection GEMM (f16), register-prefetched (proven)
// ---------------------------------------------------------------------------
#define PLDA 40

__global__ __launch_bounds__(256) void proj_kernel(const float* __restrict__ H0,
                                                   const float* __restrict__ X0) {
    const int z = blockIdx.y;
    const float* A = z ? X0 : H0;
    const __half* W = g_Wt[z];
    __half* Out = z ? g_Kh : g_Qh;
    const int row0 = blockIdx.x * 128;

    __shared__ __half As[128 * PLDA];
    __shared__ __half Bs[128 * PLDA];

    const int tid = threadIdx.x;
    const int wid = tid >> 5, lane = tid & 31;
    const int warp_m = wid >> 2, warp_n = wid & 3;
    const int q = lane >> 2, r = lane & 3;

    float c[4][4][4];
#pragma unroll
    for (int mi = 0; mi < 4; mi++)
#pragma unroll
        for (int ni = 0; ni < 4; ni++)
#pragma unroll
            for (int j = 0; j < 4; j++) c[mi][ni][j] = 0.f;

    const int arow = tid >> 3, ac4 = tid & 7;
    const int brow0 = tid >> 4, bcc = tid & 15;

    float4 av[4];
    uint32_t bv[8];
#pragma unroll
    for (int i = 0; i < 4; i++)
        av[i] = *(const float4*)&A[(size_t)(row0 + arow + i * 32) * Ddim + ac4 * 4];
#pragma unroll
    for (int i = 0; i < 8; i++)
        bv[i] = *(const uint32_t*)&W[(brow0 + i * 16) * Ddim + bcc * 2];

    for (int k0 = 0; k0 < Ddim; k0 += 32) {
        __syncthreads();
#pragma unroll
        for (int i = 0; i < 4; i++) {
            __half2 p0, p1;
            p0.x = __float2half(av[i].x); p0.y = __float2half(av[i].y);
            p1.x = __float2half(av[i].z); p1.y = __float2half(av[i].w);
            *(__half2*)&As[(arow + i * 32) * PLDA + ac4 * 4]     = p0;
            *(__half2*)&As[(arow + i * 32) * PLDA + ac4 * 4 + 2] = p1;
        }
#pragma unroll
        for (int i = 0; i < 8; i++)
            *(uint32_t*)&Bs[(brow0 + i * 16) * PLDA + bcc * 2] = bv[i];
        __syncthreads();

        if (k0 + 32 < Ddim) {
#pragma unroll
            for (int i = 0; i < 4; i++)
                av[i] = *(const float4*)&A[(size_t)(row0 + arow + i * 32) * Ddim + k0 + 32 + ac4 * 4];
#pragma unroll
            for (int i = 0; i < 8; i++)
                bv[i] = *(const uint32_t*)&W[(brow0 + i * 16) * Ddim + k0 + 32 + bcc * 2];
        }

#pragma unroll
        for (int ks = 0; ks < 32; ks += 16) {
            uint32_t af[4][4], bfg[4][2];
#pragma unroll
            for (int mi = 0; mi < 4; mi++) {
                const __half* p = &As[(warp_m * 64 + mi * 16 + q) * PLDA + ks + 2 * r];
                af[mi][0] = *(const uint32_t*)p;
                af[mi][1] = *(const uint32_t*)(p + 8 * PLDA);
                af[mi][2] = *(const uint32_t*)(p + 8);
                af[mi][3] = *(const uint32_t*)(p + 8 * PLDA + 8);
            }
#pragma unroll
            for (int ni = 0; ni < 4; ni++) {
                const __half* p = &Bs[(warp_n * 32 + ni * 8 + q) * PLDA + ks + 2 * r];
                bfg[ni][0] = *(const uint32_t*)p;
                bfg[ni][1] = *(const uint32_t*)(p + 8);
            }
#pragma unroll
            for (int mi = 0; mi < 4; mi++)
#pragma unroll
                for (int ni = 0; ni < 4; ni++)
                    mma_f16(c[mi][ni], af[mi], bfg[ni]);
        }
    }

#pragma unroll
    for (int mi = 0; mi < 4; mi++) {
        int row = row0 + warp_m * 64 + mi * 16 + q;
#pragma unroll
        for (int ni = 0; ni < 4; ni++) {
            int col = warp_n * 32 + ni * 8 + 2 * r;
            __half2 v0, v1;
            v0.x = __float2half(c[mi][ni][0]); v0.y = __float2half(c[mi][ni][1]);
            v1.x = __float2half(c[mi][ni][2]); v1.y = __float2half(c[mi][ni][3]);
            *(__half2*)&Out[(size_t)row * QKdim + col]        = v0;
            *(__half2*)&Out[(size_t)(row + 8) * QKdim + col]  = v1;
        }
    }
}

// ---------------------------------------------------------------------------
// K2: sumexp — warp-quad split.  grid (32 n-tiles, 8 b), 256 threads.
//   Quad g (warps 4g..4g+3) handles K rows [g*64, g*64+64) of every chunk,
//   with private double-buffered 64-row tiles and named-barrier sync.
// ---------------------------------------------------------------------------
#define CEX   (0.08838834764831845f * 1.4426950408889634f)   // 128^-0.5 * log2(e)
#define KLDB  272
#define QTILE (128 * KLDB)           // 34816
#define HTILE (64 * KLDB)            // 17408
#define SMEM_S (QTILE + 4 * HTILE)   // 104448

// stage 64 rows x 128 f16 by 128 threads (quad-local tid128)
__device__ __forceinline__ void stage64(uint32_t sdst, const __half* g, int t128) {
#pragma unroll
    for (int i = 0; i < 8; i++) {
        int lin = t128 + i * 128;
        int row = lin >> 4, cc = lin & 15;
        CP_ASYNC16(sdst + row * KLDB + cc * 16, g + row * 128 + cc * 8);
    }
}

__global__ __launch_bounds__(256, 2) void sumexp_kernel() {
    const uint32_t sb = smem_u32(s_dyn);
    const uint32_t sQ = sb;
    __shared__ float red[128];

    const int n0 = blockIdx.x * 128;
    const int b = blockIdx.y;
    const int tid = threadIdx.x;
    const int wid = tid >> 5, lane = tid & 31;
    const int quad = wid >> 2;                  // 0 or 1
    const int t128 = tid & 127;
    const int warp_m = (wid >> 1) & 1;          // Q-row half within quad
    const int warp_n = wid & 1;                 // K-row 32-group within quad
    const int q = lane >> 2, r = lane & 3;

    const __half* Qg = g_Qh + ((size_t)(b * Ndim) + n0) * QKdim;
    const __half* Kg = g_Kh + (size_t)(b * Ndim) * QKdim + (size_t)quad * 64 * 128;

    const uint32_t buf0 = sQ + QTILE + quad * 2 * HTILE;
    const uint32_t buf1 = buf0 + HTILE;
    const int barid = 1 + quad;

    // prologue: Q (all 256 threads) + this quad's chunk0/chunk1 halves
    {
#pragma unroll
        for (int i = 0; i < 8; i++) {
            int lin = tid + i * 256;
            int row = lin >> 4, cc = lin & 15;
            CP_ASYNC16(sQ + row * KLDB + cc * 16, Qg + row * 128 + cc * 8);
        }
        stage64(buf0, Kg, t128);
        CP_COMMIT();                 // G0 = Q part + chunk0 half
        stage64(buf1, Kg + 128 * 128, t128);
        CP_COMMIT();                 // G1 = chunk1 half
        CP_WAIT1();                  // G0 done
        __syncthreads();             // Q + chunk0 visible to all
    }

    const int arow = warp_m * 64 + ((lane >> 3) & 1) * 8 + (lane & 7);
    const uint32_t acol = (lane >> 4) * 16;
    uint32_t aaddr[4];
#pragma unroll
    for (int mi = 0; mi < 4; mi++) aaddr[mi] = sQ + (arow + mi * 16) * KLDB + acol;
    const int brow = warp_n * 32 + ((lane >> 4) & 1) * 8 + (lane & 7);
    const uint32_t boff = brow * KLDB + ((lane >> 3) & 1) * 16;

    float rs[8];
#pragma unroll
    for (int i = 0; i < 8; i++) rs[i] = 0.f;

    for (int mc = 0; mc < 32; mc++) {
        const uint32_t kbase = ((mc & 1) ? buf1 : buf0) + boff;

        float c[4][4][4];
#pragma unroll
        for (int mi = 0; mi < 4; mi++)
#pragma unroll
            for (int ni = 0; ni < 4; ni++)
#pragma unroll
                for (int j = 0; j < 4; j++) c[mi][ni][j] = 0.f;

#pragma unroll
        for (int kk = 0; kk < 8; kk++) {
            const uint32_t ko = kk * 32;
            uint32_t af[4][4], bq[2][4];
#pragma unroll
            for (int mi = 0; mi < 4; mi++) ldsm_x4(af[mi], aaddr[mi] + ko);
#pragma unroll
            for (int np = 0; np < 2; np++) ldsm_x4(bq[np], kbase + np * 16 * KLDB + ko);
#pragma unroll
            for (int mi = 0; mi < 4; mi++)
#pragma unroll
                for (int ni = 0; ni < 4; ni++)
                    mma_f16(c[mi][ni], af[mi], &bq[ni >> 1][(ni & 1) * 2]);
        }

#pragma unroll
        for (int mi = 0; mi < 4; mi++) {
            float s0 = 0.f, s1 = 0.f;
#pragma unroll
            for (int ni = 0; ni < 4; ni++) {
                s0 += ex2f(c[mi][ni][0] * CEX) + ex2f(c[mi][ni][1] * CEX);
                s1 += ex2f(c[mi][ni][2] * CEX) + ex2f(c[mi][ni][3] * CEX);
            }
            rs[mi * 2] += s0; rs[mi * 2 + 1] += s1;
        }

        BAR_QUAD(barid);             // quad done reading buffer mc&1
        if (mc + 2 < 32)
            stage64((mc & 1) ? buf1 : buf0, Kg + (size_t)(mc + 2) * 128 * 128, t128);
        CP_COMMIT();
        CP_WAIT1();                  // chunk mc+1 half (this thread's copies)
        BAR_QUAD(barid);             // visible quad-wide
    }

    // reduce across lanes sharing each row (lane & 3)
#pragma unroll
    for (int i = 0; i < 8; i++) {
        rs[i] += __shfl_xor_sync(0xffffffffu, rs[i], 1);
        rs[i] += __shfl_xor_sync(0xffffffffu, rs[i], 2);
    }
    if (tid < 128) red[tid] = 0.f;
    __syncthreads();
    if (r == 0) {
#pragma unroll
        for (int mi = 0; mi < 4; mi++) {
            atomicAdd(&red[warp_m * 64 + mi * 16 + q],     rs[mi * 2]);
            atomicAdd(&red[warp_m * 64 + mi * 16 + q + 8], rs[mi * 2 + 1]);
        }
    }
    __syncthreads();
    if (tid < 128) g_sumexp[b * Ndim + n0 + tid] = red[tid];
    __syncthreads();
    for (int s = 64; s > 0; s >>= 1) {
        if (tid < s) red[tid] += red[tid + s];
        __syncthreads();
    }
    if (tid == 0) g_tsum[b * 32 + blockIdx.x] = red[0];
}

// ---------------------------------------------------------------------------
// K3: out-GEMM.  grid (32 kc, 8 b), 256 threads, n-chunk 128, occ 2.
// ---------------------------------------------------------------------------
#define NCH 128                       // n-chunk
#define CA_LD 272                     // coef row stride bytes (128 f16 + pad)
#define HS_LD 528                     // Hs row stride bytes (256 f16 + pad)
#define CF_BYTES (32 * CA_LD)         // 8704
#define HS_BYTES (32 * HS_LD)         // 16896 (32-row subchunk)
#define SMEM_O (CF_BYTES + 2 * HS_BYTES + 32 * 8 * 4)   // 43520

__global__ __launch_bounds__(256) void outgemm_kernel(const float* __restrict__ H0) {
    __half* coefA = (__half*)s_dyn;
    __half* HsBuf[2] = { (__half*)(s_dyn + CF_BYTES),
                         (__half*)(s_dyn + CF_BYTES + HS_BYTES) };
    float* csred = (float*)(s_dyn + CF_BYTES + 2 * HS_BYTES);

    const int kc = blockIdx.x, b = blockIdx.y;
    const int n0 = kc * NCH;
    const int tid = threadIdx.x;
    const int wid = tid >> 5, lane = tid & 31;

    const uint32_t sCoef = smem_u32(coefA);
    const uint32_t sHs0 = smem_u32(HsBuf[0]);
    const uint32_t sHs1 = smem_u32(HsBuf[1]);

    // ---- coef [32 m x 128 k] f16 ----
#pragma unroll
    for (int i = 0; i < 16; i++) {
        int lin = tid + i * 256;                 // 4096
        int m = lin >> 7, k = lin & 127;
        float v = g_slotw[m * Ndim + n0 + k] * g_sumexp[b * Ndim + n0 + k];
        coefA[m * (CA_LD / 2) + k] = __float2half(v);
    }
    __syncthreads();

    // ---- csum[m] (deterministic) ----
    {
        int m = tid >> 3, g = tid & 7;
        float s = 0.f;
#pragma unroll
        for (int j = 0; j < 16; j++)
            s += __half2float(coefA[m * (CA_LD / 2) + g + j * 8]);
        csred[m * 8 + g] = s;
    }
    __syncthreads();
    if (tid < 32) {
        float s = 0.f;
#pragma unroll
        for (int g = 0; g < 8; g++) s += csred[tid * 8 + g];
        g_csum[(b * 32 + kc) * 32 + tid] = s;
    }

    const int a_r = ((lane >> 3) & 1) * 8 + (lane & 7);
    const uint32_t a_c = (lane >> 4) * 16;
    uint32_t aad[2];
#pragma unroll
    for (int mi = 0; mi < 2; mi++)
        aad[mi] = sCoef + (mi * 16 + a_r) * CA_LD + a_c;
    const int d0 = wid * 32;
    const int b_k = ((lane >> 3) & 1) * 8 + (lane & 7);
    const uint32_t b_dofs = (lane >> 4) * 8;

    float c[2][4][4];
#pragma unroll
    for (int mi = 0; mi < 2; mi++)
#pragma unroll
        for (int ni = 0; ni < 4; ni++)
#pragma unroll
            for (int j = 0; j < 4; j++) c[mi][ni][j] = 0.f;

    const float* Hbase = H0 + ((size_t)b * Ndim + n0) * Ddim;

    // preload sub-chunk 0 (32 n x 256 d)
#pragma unroll
    for (int i = 0; i < 16; i++) {
        int lin = tid + i * 256;                 // 4096 half2
        int n = lin >> 7, dq = lin & 127;
        float2 v = *(const float2*)&Hbase[(size_t)n * Ddim + dq * 2];
        __half2 h; h.x = __float2half(v.x); h.y = __float2half(v.y);
        *(__half2*)&HsBuf[0][n * (HS_LD / 2) + dq * 2] = h;
    }
    __syncthreads();

    for (int sc = 0; sc < 4; sc++) {
        const uint32_t sH = (sc & 1) ? sHs1 : sHs0;
        if (sc + 1 < 4) {
            __half* Hn = HsBuf[(sc + 1) & 1];
            const float* Hg = Hbase + (size_t)(sc + 1) * 32 * Ddim;
#pragma unroll
            for (int i = 0; i < 16; i++) {
                int lin = tid + i * 256;
                int n = lin >> 7, dq = lin & 127;
                float2 v = *(const float2*)&Hg[(size_t)n * Ddim + dq * 2];
                __half2 h; h.x = __float2half(v.x); h.y = __float2half(v.y);
                *(__half2*)&Hn[n * (HS_LD / 2) + dq * 2] = h;
            }
        }
#pragma unroll
        for (int kk = 0; kk < 2; kk++) {
            const int kg = sc * 32 + kk * 16;
            uint32_t af[2][4], bq[2][4];
#pragma unroll
            for (int mi = 0; mi < 2; mi++) ldsm_x4(af[mi], aad[mi] + kg * 2);
#pragma unroll
            for (int np = 0; np < 2; np++)
                ldsm_x4_trans(bq[np], sH + (kk * 16 + b_k) * HS_LD
                                         + (d0 + np * 16 + b_dofs) * 2);
#pragma unroll
            for (int mi = 0; mi < 2; mi++)
#pragma unroll
                for (int ni = 0; ni < 4; ni++)
                    mma_f16(c[mi][ni], af[mi], &bq[ni >> 1][(ni & 1) * 2]);
        }
        __syncthreads();
    }

    // ---- store partial [32 m x 256 d] ----
    const int q = lane >> 2, r = lane & 3;
    float* P = &g_part[((size_t)(b * 32 + kc) * Mdim) * Ddim];
#pragma unroll
    for (int mi = 0; mi < 2; mi++) {
        int row = mi * 16 + q;
#pragma unroll
        for (int ni = 0; ni < 4; ni++) {
            int col = d0 + ni * 8 + 2 * r;
            *(float2*)&P[row * Ddim + col]       = make_float2(c[mi][ni][0], c[mi][ni][1]);
            *(float2*)&P[(row + 8) * Ddim + col] = make_float2(c[mi][ni][2], c[mi][ni][3]);
        }
    }
}

// ---------------------------------------------------------------------------
// K4: reduce partials + divisor + divide.  grid 256 = (b,m), 256 thr = d.
// ---------------------------------------------------------------------------
__global__ void reduce_out_kernel(float* __restrict__ out) {
    const int bm = blockIdx.x;
    const int b = bm >> 5, m = bm & 31;
    const int d = threadIdx.x;
    __shared__ float snorm;

    if (d == 0) {
        float T = 0.f;
#pragma unroll
        for (int t = 0; t < 32; t++) T += g_tsum[b * 32 + t];
        float s = 0.f;
#pragma unroll
        for (int kc = 0; kc < 32; kc++) s += g_csum[(b * 32 + kc) * 32 + m];
        snorm = s + 1e-6f * T;
    }
    float s = 0.f;
#pragma unroll
    for (int kc = 0; kc < 32; kc++)
        s += g_part[((size_t)(b * 32 + kc) * Mdim + m) * Ddim + d];
    __syncthreads();
    out[(bm << 8) + d] = s / snorm;
}

// ---------------------------------------------------------------------------
// launch
// ---------------------------------------------------------------------------
extern "C" void kernel_launch(void* const* d_in, const int* in_sizes, int n_in,
                              void* d_out, int out_size) {
    const float* X0   = (const float*)d_in[0];
    const float* H0   = (const float*)d_in[1];
    const float* Wq   = (const float*)d_in[2];
    const float* Wk   = (const float*)d_in[3];
    const float* slot = (const float*)d_in[4];
    float* out = (float*)d_out;

    cudaFuncSetAttribute(sumexp_kernel, cudaFuncAttributeMaxDynamicSharedMemorySize, SMEM_S);
    cudaFuncSetAttribute(outgemm_kernel, cudaFuncAttributeMaxDynamicSharedMemorySize, SMEM_O);

    prep_kernel<<<160, 256>>>(Wq, Wk, slot);
    proj_kernel<<<dim3(256, 2), 256>>>(H0, X0);
    sumexp_kernel<<<dim3(32, 8), 256, SMEM_S>>>();
    outgemm_kernel<<<dim3(32, 8), 256, SMEM_O>>>(H0);
    reduce_out_kernel<<<256, 256>>>(out);
    (void)in_sizes; (void)n_in; (void)out_size;
}